// round 15
// baseline (speedup 1.0000x reference)
#include <cuda_runtime.h>
#include <math.h>

#define B_    512
#define L_    37500
#define T_    74
#define STEP_ 500
#define NF_   501
#define NMEL_ 64
#define KP_   512   // padded k-pitch for scratch (guard-free float4 transpose loads)
#define FBUF_ 9216  // per-frame smem bytes: Yc[0,4200) Zc[4200,9200)

// ---------------- scratch (device globals; no allocation) ----------------
__device__ float  g_tmp[(size_t)B_ * T_ * KP_];   // log-PSD in [b][t][k] layout
__device__ float  g_env[B_ * NF_];
__device__ float  g_psumS[B_ * 32], g_psumS2[B_ * 32];
__device__ float  g_psumC[B_ * 24], g_psumC2[B_ * 24];
__device__ float  g_aS[32], g_cS[32], g_aC[24], g_cC[24];
__device__ int    g_centers[NMEL_];
__device__ float  g_win[1000];
__device__ float4 g_twB[21 * 2];    // e^{-2pi i k r/40},  k=1..4
__device__ float4 g_twC1[40 * 2];   // e^{-2pi i k r/200}
__device__ float4 g_twC2[200 * 2];  // e^{-2pi i k m/1000}

// ---------------- init: mel centers, window, twiddle tables (fp64) ----------------
// Idempotent; launched 3x so k_spec is the 4th launch (ncu capture slot).
__global__ void k_init() {
    int i = blockIdx.x * blockDim.x + threadIdx.x;
    if (i < NMEL_) {
        if (i == 63) g_centers[63] = -1;   // pts has only 63 entries -> row 63 zero
        else {
            double f;
            if (i < 21)       f = 0.1 + 0.4 * (double)i / 20.0;
            else if (i < 31)  f = 0.5 + 0.3 * (double)(i - 21) / 9.0;
            else              f = 0.8 + 2.2 * (double)(i - 31) / 31.0;
            double fr = 125.0 / 2.0 / (double)NF_;
            g_centers[i] = (int)(f / fr);
        }
    }
    if (i < 1000)
        g_win[i] = (float)(0.5 - 0.5 * cos(6.283185307179586476925287 * (double)i / 1000.0));
    if (i < 21) {
        double th = -6.283185307179586476925287 * (double)i / 40.0;
        g_twB[2*i]   = make_float4((float)cos(th),   (float)sin(th),   (float)cos(2*th), (float)sin(2*th));
        g_twB[2*i+1] = make_float4((float)cos(3*th), (float)sin(3*th), (float)cos(4*th), (float)sin(4*th));
    }
    if (i < 40) {
        double th = -6.283185307179586476925287 * (double)i / 200.0;
        g_twC1[2*i]   = make_float4((float)cos(th),   (float)sin(th),   (float)cos(2*th), (float)sin(2*th));
        g_twC1[2*i+1] = make_float4((float)cos(3*th), (float)sin(3*th), (float)cos(4*th), (float)sin(4*th));
    }
    if (i < 200) {
        double th = -6.283185307179586476925287 * (double)i / 1000.0;
        g_twC2[2*i]   = make_float4((float)cos(th),   (float)sin(th),   (float)cos(2*th), (float)sin(2*th));
        g_twC2[2*i+1] = make_float4((float)cos(3*th), (float)sin(3*th), (float)cos(4*th), (float)sin(4*th));
    }
}

// ---------------- spectrogram: one block per TWO (b, t) frames ----------------
// R13 body; __launch_bounds__(128, 8) forces <=64 regs for 8 blocks/SM (50% occ).
__global__ void __launch_bounds__(128, 8) k_spec(const float* __restrict__ x) {
    const int f0 = blockIdx.x * 2;
    __shared__ __align__(16) char sbuf[2][FBUF_];
    __shared__ float red[2][4];
    const int tid = threadIdx.x;
    const int wid = tid >> 5;

    // ---- load both frames (125-stride layout) + warp-reduce for detrend mean ----
    float v[2][8];
#pragma unroll
    for (int fr = 0; fr < 2; ++fr) {
        const int f = f0 + fr;
        const int b = f / T_, t = f % T_;
        const float* xin = x + (size_t)b * L_ + (size_t)t * STEP_;
        float s = 0.f;
        if (tid < 125) {
#pragma unroll
            for (int u = 0; u < 8; ++u) { float vv = xin[125 * u + tid]; v[fr][u] = vv; s += vv; }
        }
#pragma unroll
        for (int o = 16; o; o >>= 1) s += __shfl_down_sync(0xffffffffu, s, o);
        if ((tid & 31) == 0) red[fr][wid] = s;
    }
    __syncthreads();

    // ---- Stage A: detrend + window + 125 real 8-point DFTs, from registers ----
#pragma unroll
    for (int fr = 0; fr < 2; ++fr) {
        float2* Zc = (float2*)(sbuf[fr] + 4200);
        const float mean = (red[fr][0] + red[fr][1] + red[fr][2] + red[fr][3]) * 1e-3f;
        if (tid < 125) {
            float e[8];
#pragma unroll
            for (int u = 0; u < 8; ++u)
                e[u] = (v[fr][u] - mean) * __ldg(&g_win[125 * u + tid]);
            float a0 = e[0] + e[4], a1 = e[1] + e[5], a2 = e[2] + e[6], a3 = e[3] + e[7];
            float b0 = e[0] - e[4], b1 = e[1] - e[5], b2 = e[2] - e[6], b3 = e[3] - e[7];
            float s1 = a0 + a2, s2 = a1 + a3;
            const float RC = 0.70710678118654752f;
            float t1c = RC * (b1 - b3);
            float t2c = RC * (b1 + b3);
            Zc[tid]       = make_float2(s1 + s2,  0.f);
            Zc[125 + tid] = make_float2(b0 + t1c, -(t2c + b2));
            Zc[250 + tid] = make_float2(a0 - a2,  -(a1 - a3));
            Zc[375 + tid] = make_float2(b0 - t1c, b2 - t2c);
            Zc[500 + tid] = make_float2(s1 - s2,  0.f);
        }
    }
    __syncthreads();

    // ---- Stage B: Y[r][q], r = 0..20; 5 q-accumulators sweep v ----
#pragma unroll
    for (int fr = 0; fr < 2; ++fr) {
        float2* Yc = (float2*)sbuf[fr];
        const float2* Zc = (const float2*)(sbuf[fr] + 4200);
        if (tid < 105) {
            const int r  = tid % 21;
            const int q0 = (tid / 21) * 5;
            float4 ta = __ldg(&g_twB[2*r]), tb = __ldg(&g_twB[2*r + 1]);
            int j = r % 8;
            int jj; float zsg;
            if (j <= 4) { jj = j;     zsg =  1.f; }
            else        { jj = 8 - j; zsg = -1.f; }
            const float2* zb = Zc + jj * 125 + q0;

            float ar[5], ai[5];
#pragma unroll
            for (int dq = 0; dq < 5; ++dq) { float2 z = zb[dq]; ar[dq] = z.x; ai[dq] = z.y; }

            float wrv[4] = {ta.x, ta.z, tb.x, tb.z};
            float wiv[4] = {zsg * ta.y, zsg * ta.w, zsg * tb.y, zsg * tb.w};
#pragma unroll
            for (int vv = 1; vv < 5; ++vv) {
                const float2* zv = zb + 25 * vv;
                float cr = wrv[vv-1], ci = wiv[vv-1];
#pragma unroll
                for (int dq = 0; dq < 5; ++dq) {
                    float2 z = zv[dq];
                    ar[dq] += cr * z.x - ci * z.y;
                    ai[dq] += cr * z.y + ci * z.x;
                }
            }
#pragma unroll
            for (int dq = 0; dq < 5; ++dq)
                Yc[r * 25 + q0 + dq] = make_float2(ar[dq], zsg * ai[dq]);
        }
    }
    __syncthreads();

    // ---- Stages C1+C2 fused: thread (fr, r) owns all b5, s for its r ----
    if (tid < 80) {
        const float C1 = 0.30901699437494745f, C2 = -0.80901699437494745f;
        const float S1 = 0.95105651629515357f, S2 =  0.58778525229247313f;
        const int fr = tid / 40, r = tid - fr * 40;
        const float2* Yc = (const float2*)sbuf[fr];
        int rr; float ysg;
        if (r <= 20) { rr = r;      ysg =  1.f; }
        else         { rr = 40 - r; ysg = -1.f; }
        float4 ta = __ldg(&g_twC1[2*r]), tb = __ldg(&g_twC1[2*r + 1]);
        const float2* yb = Yc + rr * 25;

        float Wr[5][5], Wi[5][5];   // [b5][s]
#pragma unroll
        for (int b5 = 0; b5 < 5; ++b5) {
            float2 Y0 = yb[b5], P1 = yb[5 + b5], P2 = yb[10 + b5], P3 = yb[15 + b5], P4 = yb[20 + b5];
            float y0r = Y0.x, y0i = ysg * Y0.y;
            float p1i = ysg * P1.y, p2i = ysg * P2.y, p3i = ysg * P3.y, p4i = ysg * P4.y;

            float y1r = ta.x * P1.x - ta.y * p1i, y1i = ta.x * p1i + ta.y * P1.x;
            float y2r = ta.z * P2.x - ta.w * p2i, y2i = ta.z * p2i + ta.w * P2.x;
            float y3r = tb.x * P3.x - tb.y * p3i, y3i = tb.x * p3i + tb.y * P3.x;
            float y4r = tb.z * P4.x - tb.w * p4i, y4i = tb.z * p4i + tb.w * P4.x;

            float t1r = y1r + y4r, t1i = y1i + y4i;
            float t2r = y2r + y3r, t2i = y2i + y3i;
            float t3r = y1r - y4r, t3i = y1i - y4i;
            float t4r = y2r - y3r, t4i = y2i - y3i;
            float Ar = C1 * t1r + C2 * t2r, Ai = C1 * t1i + C2 * t2i;
            float Br = C2 * t1r + C1 * t2r, Bi = C2 * t1i + C1 * t2i;
            float Cr = S1 * t3r + S2 * t4r, Ci = S1 * t3i + S2 * t4i;
            float Dr = S2 * t3r - S1 * t4r, Di = S2 * t3i - S1 * t4i;

            Wr[b5][0] = y0r + t1r + t2r;  Wi[b5][0] = y0i + t1i + t2i;
            Wr[b5][1] = y0r + Ar + Ci;    Wi[b5][1] = y0i + Ai - Cr;
            Wr[b5][2] = y0r + Br + Di;    Wi[b5][2] = y0i + Bi - Dr;
            Wr[b5][3] = y0r + Br - Di;    Wi[b5][3] = y0i + Bi + Dr;
            Wr[b5][4] = y0r + Ar - Ci;    Wi[b5][4] = y0i + Ai + Cr;
        }

        float* outrow = g_tmp + (size_t)(f0 + fr) * KP_;
        const float SC2 = 2.f / 46875.f;   // fs * sum(win^2) = 125 * 375
#pragma unroll
        for (int s = 0; s < 5; ++s) {
            const int m = r + 40 * s;
            float4 tc = __ldg(&g_twC2[2*m]), td = __ldg(&g_twC2[2*m + 1]);

            float z0r = Wr[0][s], z0i = Wi[0][s];
            float z1r = tc.x * Wr[1][s] - tc.y * Wi[1][s], z1i = tc.x * Wi[1][s] + tc.y * Wr[1][s];
            float z2r = tc.z * Wr[2][s] - tc.w * Wi[2][s], z2i = tc.z * Wi[2][s] + tc.w * Wr[2][s];
            float z3r = td.x * Wr[3][s] - td.y * Wi[3][s], z3i = td.x * Wi[3][s] + td.y * Wr[3][s];
            float z4r = td.z * Wr[4][s] - td.w * Wi[4][s], z4i = td.z * Wi[4][s] + td.w * Wr[4][s];

            float t1r = z1r + z4r, t1i = z1i + z4i;
            float t2r = z2r + z3r, t2i = z2i + z3i;
            float t3r = z1r - z4r, t3i = z1i - z4i;
            float t4r = z2r - z3r, t4i = z2i - z3i;

            {   // c = 0 : k = m
                float Xr = z0r + t1r + t2r, Xi = z0i + t1i + t2i;
                float sc = (m == 0) ? (1.f / 46875.f) : SC2;
                outrow[m] = __logf((Xr * Xr + Xi * Xi) * sc + 1e-8f);
            }
            float Ar = C1 * t1r + C2 * t2r, Ai = C1 * t1i + C2 * t2i;
            float Cr = S1 * t3r + S2 * t4r, Ci = S1 * t3i + S2 * t4i;
            {   // c = 1 : k = m + 200
                float Xr = z0r + Ar + Ci, Xi = z0i + Ai - Cr;
                outrow[m + 200] = __logf((Xr * Xr + Xi * Xi) * SC2 + 1e-8f);
            }
            if (m <= 100) {  // c = 2 : k = m + 400
                float Br = C2 * t1r + C1 * t2r, Bi = C2 * t1i + C1 * t2i;
                float Dr = S2 * t3r - S1 * t4r, Di = S2 * t3i - S1 * t4i;
                float Xr = z0r + Br + Di, Xi = z0i + Bi - Dr;
                float sc = (m == 100) ? (1.f / 46875.f) : SC2;
                outrow[m + 400] = __logf((Xr * Xr + Xi * Xi) * sc + 1e-8f);
            }
        }
    }
}

// ---------------- transpose [b][t][k] -> spec[b][k][t]; fused env + mel ----------------
// 64-wide k tiles, float4 loads; division-free store loop via incremental (kx, tt) carry.
__global__ void __launch_bounds__(256) k_transpose(float* __restrict__ spec,
                                                   float* __restrict__ mel) {
    const int bb = blockIdx.x >> 3;
    const int k0 = (blockIdx.x & 7) * 64;
    const int tid = threadIdx.x;
    __shared__ float tile[T_][65];

    for (int i = tid; i < T_ * 16; i += 256) {
        int tt = i >> 4, j = i & 15;
        float4 vv = *(const float4*)(g_tmp + ((size_t)bb * T_ + tt) * KP_ + k0 + j * 4);
        tile[tt][j * 4 + 0] = vv.x;
        tile[tt][j * 4 + 1] = vv.y;
        tile[tt][j * 4 + 2] = vv.z;
        tile[tt][j * 4 + 3] = vv.w;
    }
    __syncthreads();

    // store: i = kx*74 + tt advances by 256 = 3*74 + 34 per step (no div/mod in loop)
    {
        const int kxmax = (k0 + 64 <= NF_) ? 64 : (NF_ - k0);
        float* outb = spec + ((size_t)bb * NF_ + k0) * T_;
        int kx = tid / T_;             // one-time (tid < 256 -> kx in 0..3)
        int tt = tid - kx * T_;
        while (kx < kxmax) {
            outb[kx * T_ + tt] = tile[tt][kx];
            kx += 3; tt += 34;
            if (tt >= T_) { tt -= T_; ++kx; }
        }
    }
    if (tid < 64) {
        int k = k0 + tid;
        if (k < NF_) {
            float s = 0.f;
            for (int tt = 0; tt < T_; ++tt) s += tile[tt][tid];
            g_env[bb * NF_ + k] = s * (1.f / (float)T_);
        }
    }
    if (k0 == 0) {   // mel gather: all centers are in [0, 25); same carry trick (m <= 63)
        int m = tid / T_;
        int tt = tid - m * T_;
        float* melb = mel + (size_t)bb * NMEL_ * T_;
        while (m < NMEL_) {
            int c = g_centers[m];
            melb[m * T_ + tt] = (c >= 0) ? tile[tt][c] : 0.f;
            m += 3; tt += 34;
            if (tt >= T_) { tt -= T_; ++m; }
        }
    }
}

// ---------------- BN stats: single pass, float partials (sum, sumsq) ----------------
__global__ void __launch_bounds__(256) k_bnstats(const float* __restrict__ w5, const float* __restrict__ b5,
                                                 const float* __restrict__ w7, const float* __restrict__ b7) {
    const int b = blockIdx.x, tid = threadIdx.x;
    __shared__ float e[NF_ + 4];
    __shared__ float cp[24];
    for (int i = tid; i < NF_ + 4; i += 256) {
        int f = i - 2;
        e[i] = (f >= 0 && f < NF_) ? g_env[b * NF_ + f] : 0.f;
    }
    if (tid < 24) {
        int j = tid - 3;
        cp[tid] = (j >= 0 && j < 18) ? g_env[b * NF_ + 6 + j] : 0.f;
    }
    __syncthreads();

    {
        const int o = tid >> 3, sub = tid & 7;
        float wv[5];
#pragma unroll
        for (int k = 0; k < 5; ++k) wv[k] = w5[o * 5 + k];
        const float bb = b5[o];
        float s = 0.f, s2 = 0.f;
        for (int l = sub; l < NF_; l += 8) {
            float y = bb;
#pragma unroll
            for (int k = 0; k < 5; ++k) y += wv[k] * e[l + k];
            s += y; s2 += y * y;
        }
#pragma unroll
        for (int d = 4; d; d >>= 1) {
            s  += __shfl_down_sync(0xffffffffu, s,  d, 8);
            s2 += __shfl_down_sync(0xffffffffu, s2, d, 8);
        }
        if (sub == 0) { g_psumS[b * 32 + o] = s; g_psumS2[b * 32 + o] = s2; }
    }
    if (tid < 24) {
        const int oc = tid;
        float s = 0.f, s2 = 0.f;
        for (int l = 0; l < 18; ++l) {
            float y = b7[oc];
#pragma unroll
            for (int k = 0; k < 7; ++k) y += w7[oc * 7 + k] * cp[l + k];
            s += y; s2 += y * y;
        }
        g_psumC[b * 24 + oc] = s; g_psumC2[b * 24 + oc] = s2;
    }
}

// ---------------- reduce: parallel fp64 mean/var -> BN scale/shift ----------------
__global__ void __launch_bounds__(896) k_reduce(const float* __restrict__ gS, const float* __restrict__ btS,
                                                const float* __restrict__ gC, const float* __restrict__ btC) {
    const int t = threadIdx.x;
    const int ch = t >> 4, sub = t & 15;
    if (ch >= 56) return;
    double s = 0.0, s2 = 0.0;
    if (ch < 32) {
        for (int j = 0; j < 32; ++j) {
            int b = sub + 16 * j;
            s  += (double)g_psumS[b * 32 + ch];
            s2 += (double)g_psumS2[b * 32 + ch];
        }
    } else {
        int o = ch - 32;
        for (int j = 0; j < 32; ++j) {
            int b = sub + 16 * j;
            s  += (double)g_psumC[b * 24 + o];
            s2 += (double)g_psumC2[b * 24 + o];
        }
    }
#pragma unroll
    for (int d = 8; d; d >>= 1) {
        s  += __shfl_down_sync(0xffffffffu, s,  d, 16);
        s2 += __shfl_down_sync(0xffffffffu, s2, d, 16);
    }
    if (sub == 0) {
        if (ch < 32) {
            double N = (double)B_ * (double)NF_;
            double m = s / N;
            double var = s2 / N - m * m;
            float a = gS[ch] * rsqrtf((float)var + 1e-5f);
            g_aS[ch] = a; g_cS[ch] = btS[ch] - (float)m * a;
        } else {
            int o = ch - 32;
            double N = (double)B_ * 18.0;
            double m = s / N;
            double var = s2 / N - m * m;
            float a = gC[o] * rsqrtf((float)var + 1e-5f);
            g_aC[o] = a; g_cC[o] = btC[o] - (float)m * a;
        }
    }
}

// ---------------- finalize: spectral out, cfeat, rfeat ----------------
__global__ void __launch_bounds__(256) k_final(const float* __restrict__ w5, const float* __restrict__ b5,
                                               const float* __restrict__ w7, const float* __restrict__ b7,
                                               const float* __restrict__ w1, const float* __restrict__ b1,
                                               const float* __restrict__ w2, const float* __restrict__ b2,
                                               float* __restrict__ outSpectral,
                                               float* __restrict__ outR,
                                               float* __restrict__ outC) {
    const int b = blockIdx.x, tid = threadIdx.x;
    __shared__ float e[NF_ + 4];
    __shared__ float cp[24];
    __shared__ float ws5[160], bs5[32], aSs[32], cSs[32];
    __shared__ float rpp[9];
    __shared__ float r1p[16][7];

    for (int i = tid; i < NF_ + 4; i += 256) {
        int f = i - 2;
        e[i] = (f >= 0 && f < NF_) ? g_env[b * NF_ + f] : 0.f;
    }
    if (tid < 24) {
        int j = tid - 3;
        cp[tid] = (j >= 0 && j < 18) ? g_env[b * NF_ + 6 + j] : 0.f;
    }
    if (tid < 160) ws5[tid] = w5[tid];
    if (tid < 32) { bs5[tid] = b5[tid]; aSs[tid] = g_aS[tid]; cSs[tid] = g_cS[tid]; }
    if (tid < 9) {
        int j = tid - 2;
        rpp[tid] = (j >= 0 && j < 4) ? g_env[b * NF_ + j] : 0.f;
    }
    if (tid < 16) { r1p[tid][0] = 0.f; r1p[tid][6] = 0.f; }
    __syncthreads();

    if (tid < 80) {
        int i = tid / 5, l = tid % 5;
        float y = b1[i];
#pragma unroll
        for (int k = 0; k < 5; ++k) y += w1[i * 5 + k] * rpp[l + k];
        r1p[i][l + 1] = fmaxf(0.f, y);
    }

    for (int idx = tid; idx < 32 * NF_; idx += 256) {
        int o = idx / NF_, l = idx - o * NF_;
        float y = bs5[o];
#pragma unroll
        for (int k = 0; k < 5; ++k) y += ws5[o * 5 + k] * e[l + k];
        outSpectral[(size_t)b * 32 * NF_ + idx] = fmaxf(0.f, y * aSs[o] + cSs[o]);
    }

    if (tid < 32) {
        float val = 0.f;
        if (tid < 24) {
            const int oc = tid;
            const float a = g_aC[oc], c = g_cC[oc];
            float acc = 0.f;
            for (int l = 0; l < 18; ++l) {
                float y = b7[oc];
#pragma unroll
                for (int k = 0; k < 7; ++k) y += w7[oc * 7 + k] * cp[l + k];
                acc += fmaxf(0.f, y * a + c);
            }
            val = acc / 18.f;
        }
        outC[b * 32 + tid] = val;
    }
    __syncthreads();

    if (tid < 32) {
        const int o = tid;
        float acc = 5.f * b2[o];
        for (int i = 0; i < 16; ++i) {
#pragma unroll
            for (int l = 0; l < 5; ++l)
#pragma unroll
                for (int k = 0; k < 3; ++k)
                    acc += w2[o * 48 + i * 3 + k] * r1p[i][l + k];
        }
        outR[b * 32 + o] = acc * 0.2f;
    }
}

// ---------------- launch ----------------
extern "C" void kernel_launch(void* const* d_in, const int* in_sizes, int n_in,
                              void* d_out, int out_size) {
    (void)in_sizes; (void)n_in; (void)out_size;
    const float* x   = (const float*)d_in[0];
    const float* w5  = (const float*)d_in[1];
    const float* b5  = (const float*)d_in[2];
    const float* g5  = (const float*)d_in[3];
    const float* bt5 = (const float*)d_in[4];
    const float* w7  = (const float*)d_in[5];
    const float* b7  = (const float*)d_in[6];
    const float* g7  = (const float*)d_in[7];
    const float* bt7 = (const float*)d_in[8];
    const float* w1  = (const float*)d_in[9];
    const float* b1  = (const float*)d_in[10];
    const float* w2  = (const float*)d_in[11];
    const float* b2  = (const float*)d_in[12];

    float* out         = (float*)d_out;
    float* outMel      = out;
    float* outSpectral = outMel + (size_t)B_ * 64 * T_;
    float* outR        = outSpectral + (size_t)B_ * 32 * NF_;
    float* outC        = outR + (size_t)B_ * 32;
    float* outSpec     = outC + (size_t)B_ * 32;

    // k_init idempotent; 3x so k_spec is the 4th launch (ncu capture slot).
    k_init<<<8, 128>>>();
    k_init<<<8, 128>>>();
    k_init<<<8, 128>>>();
    k_spec<<<B_ * T_ / 2, 128>>>(x);
    k_transpose<<<B_ * 8, 256>>>(outSpec, outMel);
    k_bnstats<<<B_, 256>>>(w5, b5, w7, b7);
    k_reduce<<<1, 896>>>(g5, bt5, g7, bt7);
    k_final<<<B_, 256>>>(w5, b5, w7, b7, w1, b1, w2, b2, outSpectral, outR, outC);
}

// round 16
// speedup vs baseline: 1.2234x; 1.2234x over previous
#include <cuda_runtime.h>
#include <math.h>

#define B_    512
#define L_    37500
#define T_    74
#define STEP_ 500
#define NF_   501
#define NMEL_ 64
#define KP_   512   // padded k-pitch for scratch (guard-free float4 transpose loads)
#define FBUF_ 9216  // per-frame smem bytes: Yc[0,4200) Zc[4200,9200)

// ---------------- scratch (device globals; no allocation) ----------------
__device__ float  g_tmp[(size_t)B_ * T_ * KP_];   // log-PSD in [b][t][k] layout
__device__ float  g_env[B_ * NF_];
__device__ float  g_psumS[B_ * 32], g_psumS2[B_ * 32];
__device__ float  g_psumC[B_ * 24], g_psumC2[B_ * 24];
__device__ float  g_aS[32], g_cS[32], g_aC[24], g_cC[24];
__device__ int    g_centers[NMEL_];
__device__ float  g_win[1000];
__device__ float4 g_twB[21 * 2];    // e^{-2pi i k r/40},  k=1..4
__device__ float4 g_twC1[40 * 2];   // e^{-2pi i k r/200}
__device__ float4 g_twC2[200 * 2];  // e^{-2pi i k m/1000}

// ---------------- init: mel centers, window, twiddle tables (fp64) ----------------
__global__ void k_init() {
    int i = blockIdx.x * blockDim.x + threadIdx.x;
    if (i < NMEL_) {
        if (i == 63) g_centers[63] = -1;   // pts has only 63 entries -> row 63 zero
        else {
            double f;
            if (i < 21)       f = 0.1 + 0.4 * (double)i / 20.0;
            else if (i < 31)  f = 0.5 + 0.3 * (double)(i - 21) / 9.0;
            else              f = 0.8 + 2.2 * (double)(i - 31) / 31.0;
            double fr = 125.0 / 2.0 / (double)NF_;
            g_centers[i] = (int)(f / fr);
        }
    }
    if (i < 1000)
        g_win[i] = (float)(0.5 - 0.5 * cos(6.283185307179586476925287 * (double)i / 1000.0));
    if (i < 21) {
        double th = -6.283185307179586476925287 * (double)i / 40.0;
        g_twB[2*i]   = make_float4((float)cos(th),   (float)sin(th),   (float)cos(2*th), (float)sin(2*th));
        g_twB[2*i+1] = make_float4((float)cos(3*th), (float)sin(3*th), (float)cos(4*th), (float)sin(4*th));
    }
    if (i < 40) {
        double th = -6.283185307179586476925287 * (double)i / 200.0;
        g_twC1[2*i]   = make_float4((float)cos(th),   (float)sin(th),   (float)cos(2*th), (float)sin(2*th));
        g_twC1[2*i+1] = make_float4((float)cos(3*th), (float)sin(3*th), (float)cos(4*th), (float)sin(4*th));
    }
    if (i < 200) {
        double th = -6.283185307179586476925287 * (double)i / 1000.0;
        g_twC2[2*i]   = make_float4((float)cos(th),   (float)sin(th),   (float)cos(2*th), (float)sin(2*th));
        g_twC2[2*i+1] = make_float4((float)cos(3*th), (float)sin(3*th), (float)cos(4*th), (float)sin(4*th));
    }
}

// ---------------- spectrogram: one block per TWO (b, t) frames ----------------
// __launch_bounds__(128, 8): 64 regs, 8 blocks/SM (measured 97us, occ 43.8%).
__global__ void __launch_bounds__(128, 8) k_spec(const float* __restrict__ x) {
    const int f0 = blockIdx.x * 2;
    __shared__ __align__(16) char sbuf[2][FBUF_];
    __shared__ float red[2][4];
    const int tid = threadIdx.x;
    const int wid = tid >> 5;

    // ---- load both frames (125-stride layout) + warp-reduce for detrend mean ----
    float v[2][8];
#pragma unroll
    for (int fr = 0; fr < 2; ++fr) {
        const int f = f0 + fr;
        const int b = f / T_, t = f % T_;
        const float* xin = x + (size_t)b * L_ + (size_t)t * STEP_;
        float s = 0.f;
        if (tid < 125) {
#pragma unroll
            for (int u = 0; u < 8; ++u) { float vv = xin[125 * u + tid]; v[fr][u] = vv; s += vv; }
        }
#pragma unroll
        for (int o = 16; o; o >>= 1) s += __shfl_down_sync(0xffffffffu, s, o);
        if ((tid & 31) == 0) red[fr][wid] = s;
    }
    __syncthreads();

    // ---- Stage A: detrend + window + 125 real 8-point DFTs, from registers ----
#pragma unroll
    for (int fr = 0; fr < 2; ++fr) {
        float2* Zc = (float2*)(sbuf[fr] + 4200);
        const float mean = (red[fr][0] + red[fr][1] + red[fr][2] + red[fr][3]) * 1e-3f;
        if (tid < 125) {
            float e[8];
#pragma unroll
            for (int u = 0; u < 8; ++u)
                e[u] = (v[fr][u] - mean) * __ldg(&g_win[125 * u + tid]);
            float a0 = e[0] + e[4], a1 = e[1] + e[5], a2 = e[2] + e[6], a3 = e[3] + e[7];
            float b0 = e[0] - e[4], b1 = e[1] - e[5], b2 = e[2] - e[6], b3 = e[3] - e[7];
            float s1 = a0 + a2, s2 = a1 + a3;
            const float RC = 0.70710678118654752f;
            float t1c = RC * (b1 - b3);
            float t2c = RC * (b1 + b3);
            Zc[tid]       = make_float2(s1 + s2,  0.f);
            Zc[125 + tid] = make_float2(b0 + t1c, -(t2c + b2));
            Zc[250 + tid] = make_float2(a0 - a2,  -(a1 - a3));
            Zc[375 + tid] = make_float2(b0 - t1c, b2 - t2c);
            Zc[500 + tid] = make_float2(s1 - s2,  0.f);
        }
    }
    __syncthreads();

    // ---- Stage B: Y[r][q], r = 0..20; 5 q-accumulators sweep v ----
#pragma unroll
    for (int fr = 0; fr < 2; ++fr) {
        float2* Yc = (float2*)sbuf[fr];
        const float2* Zc = (const float2*)(sbuf[fr] + 4200);
        if (tid < 105) {
            const int r  = tid % 21;
            const int q0 = (tid / 21) * 5;
            float4 ta = __ldg(&g_twB[2*r]), tb = __ldg(&g_twB[2*r + 1]);
            int j = r % 8;
            int jj; float zsg;
            if (j <= 4) { jj = j;     zsg =  1.f; }
            else        { jj = 8 - j; zsg = -1.f; }
            const float2* zb = Zc + jj * 125 + q0;

            float ar[5], ai[5];
#pragma unroll
            for (int dq = 0; dq < 5; ++dq) { float2 z = zb[dq]; ar[dq] = z.x; ai[dq] = z.y; }

            float wrv[4] = {ta.x, ta.z, tb.x, tb.z};
            float wiv[4] = {zsg * ta.y, zsg * ta.w, zsg * tb.y, zsg * tb.w};
#pragma unroll
            for (int vv = 1; vv < 5; ++vv) {
                const float2* zv = zb + 25 * vv;
                float cr = wrv[vv-1], ci = wiv[vv-1];
#pragma unroll
                for (int dq = 0; dq < 5; ++dq) {
                    float2 z = zv[dq];
                    ar[dq] += cr * z.x - ci * z.y;
                    ai[dq] += cr * z.y + ci * z.x;
                }
            }
#pragma unroll
            for (int dq = 0; dq < 5; ++dq)
                Yc[r * 25 + q0 + dq] = make_float2(ar[dq], zsg * ai[dq]);
        }
    }
    __syncthreads();

    // ---- Stages C1+C2 fused: thread (fr, r) owns all b5, s for its r ----
    if (tid < 80) {
        const float C1 = 0.30901699437494745f, C2 = -0.80901699437494745f;
        const float S1 = 0.95105651629515357f, S2 =  0.58778525229247313f;
        const int fr = tid / 40, r = tid - fr * 40;
        const float2* Yc = (const float2*)sbuf[fr];
        int rr; float ysg;
        if (r <= 20) { rr = r;      ysg =  1.f; }
        else         { rr = 40 - r; ysg = -1.f; }
        float4 ta = __ldg(&g_twC1[2*r]), tb = __ldg(&g_twC1[2*r + 1]);
        const float2* yb = Yc + rr * 25;

        float Wr[5][5], Wi[5][5];   // [b5][s]
#pragma unroll
        for (int b5 = 0; b5 < 5; ++b5) {
            float2 Y0 = yb[b5], P1 = yb[5 + b5], P2 = yb[10 + b5], P3 = yb[15 + b5], P4 = yb[20 + b5];
            float y0r = Y0.x, y0i = ysg * Y0.y;
            float p1i = ysg * P1.y, p2i = ysg * P2.y, p3i = ysg * P3.y, p4i = ysg * P4.y;

            float y1r = ta.x * P1.x - ta.y * p1i, y1i = ta.x * p1i + ta.y * P1.x;
            float y2r = ta.z * P2.x - ta.w * p2i, y2i = ta.z * p2i + ta.w * P2.x;
            float y3r = tb.x * P3.x - tb.y * p3i, y3i = tb.x * p3i + tb.y * P3.x;
            float y4r = tb.z * P4.x - tb.w * p4i, y4i = tb.z * p4i + tb.w * P4.x;

            float t1r = y1r + y4r, t1i = y1i + y4i;
            float t2r = y2r + y3r, t2i = y2i + y3i;
            float t3r = y1r - y4r, t3i = y1i - y4i;
            float t4r = y2r - y3r, t4i = y2i - y3i;
            float Ar = C1 * t1r + C2 * t2r, Ai = C1 * t1i + C2 * t2i;
            float Br = C2 * t1r + C1 * t2r, Bi = C2 * t1i + C1 * t2i;
            float Cr = S1 * t3r + S2 * t4r, Ci = S1 * t3i + S2 * t4i;
            float Dr = S2 * t3r - S1 * t4r, Di = S2 * t3i - S1 * t4i;

            Wr[b5][0] = y0r + t1r + t2r;  Wi[b5][0] = y0i + t1i + t2i;
            Wr[b5][1] = y0r + Ar + Ci;    Wi[b5][1] = y0i + Ai - Cr;
            Wr[b5][2] = y0r + Br + Di;    Wi[b5][2] = y0i + Bi - Dr;
            Wr[b5][3] = y0r + Br - Di;    Wi[b5][3] = y0i + Bi + Dr;
            Wr[b5][4] = y0r + Ar - Ci;    Wi[b5][4] = y0i + Ai + Cr;
        }

        float* outrow = g_tmp + (size_t)(f0 + fr) * KP_;
        const float SC2 = 2.f / 46875.f;   // fs * sum(win^2) = 125 * 375
#pragma unroll
        for (int s = 0; s < 5; ++s) {
            const int m = r + 40 * s;
            float4 tc = __ldg(&g_twC2[2*m]), td = __ldg(&g_twC2[2*m + 1]);

            float z0r = Wr[0][s], z0i = Wi[0][s];
            float z1r = tc.x * Wr[1][s] - tc.y * Wi[1][s], z1i = tc.x * Wi[1][s] + tc.y * Wr[1][s];
            float z2r = tc.z * Wr[2][s] - tc.w * Wi[2][s], z2i = tc.z * Wi[2][s] + tc.w * Wr[2][s];
            float z3r = td.x * Wr[3][s] - td.y * Wi[3][s], z3i = td.x * Wi[3][s] + td.y * Wr[3][s];
            float z4r = td.z * Wr[4][s] - td.w * Wi[4][s], z4i = td.z * Wi[4][s] + td.w * Wr[4][s];

            float t1r = z1r + z4r, t1i = z1i + z4i;
            float t2r = z2r + z3r, t2i = z2i + z3i;
            float t3r = z1r - z4r, t3i = z1i - z4i;
            float t4r = z2r - z3r, t4i = z2i - z3i;

            {   // c = 0 : k = m
                float Xr = z0r + t1r + t2r, Xi = z0i + t1i + t2i;
                float sc = (m == 0) ? (1.f / 46875.f) : SC2;
                outrow[m] = __logf((Xr * Xr + Xi * Xi) * sc + 1e-8f);
            }
            float Ar = C1 * t1r + C2 * t2r, Ai = C1 * t1i + C2 * t2i;
            float Cr = S1 * t3r + S2 * t4r, Ci = S1 * t3i + S2 * t4i;
            {   // c = 1 : k = m + 200
                float Xr = z0r + Ar + Ci, Xi = z0i + Ai - Cr;
                outrow[m + 200] = __logf((Xr * Xr + Xi * Xi) * SC2 + 1e-8f);
            }
            if (m <= 100) {  // c = 2 : k = m + 400
                float Br = C2 * t1r + C1 * t2r, Bi = C2 * t1i + C1 * t2i;
                float Dr = S2 * t3r - S1 * t4r, Di = S2 * t3i - S1 * t4i;
                float Xr = z0r + Br + Di, Xi = z0i + Bi - Dr;
                float sc = (m == 100) ? (1.f / 46875.f) : SC2;
                outrow[m + 400] = __logf((Xr * Xr + Xi * Xi) * sc + 1e-8f);
            }
        }
    }
}

// ---------------- transpose [b][t][k] -> spec[b][k][t]; fused env + mel ----------------
// 64-wide k tiles, float4 loads, division-free store loops.
__global__ void __launch_bounds__(256) k_transpose(float* __restrict__ spec,
                                                   float* __restrict__ mel) {
    const int bb = blockIdx.x >> 3;
    const int k0 = (blockIdx.x & 7) * 64;
    const int tid = threadIdx.x;
    __shared__ float tile[T_][65];

    for (int i = tid; i < T_ * 16; i += 256) {
        int tt = i >> 4, j = i & 15;
        float4 vv = *(const float4*)(g_tmp + ((size_t)bb * T_ + tt) * KP_ + k0 + j * 4);
        tile[tt][j * 4 + 0] = vv.x;
        tile[tt][j * 4 + 1] = vv.y;
        tile[tt][j * 4 + 2] = vv.z;
        tile[tt][j * 4 + 3] = vv.w;
    }
    __syncthreads();

    // store: i = kx*74 + tt advances by 256 = 3*74 + 34 per step (no div/mod in loop)
    {
        const int kxmax = (k0 + 64 <= NF_) ? 64 : (NF_ - k0);
        float* outb = spec + ((size_t)bb * NF_ + k0) * T_;
        int kx = tid / T_;
        int tt = tid - kx * T_;
        while (kx < kxmax) {
            outb[kx * T_ + tt] = tile[tt][kx];
            kx += 3; tt += 34;
            if (tt >= T_) { tt -= T_; ++kx; }
        }
    }
    if (tid < 64) {
        int k = k0 + tid;
        if (k < NF_) {
            float s = 0.f;
            for (int tt = 0; tt < T_; ++tt) s += tile[tt][tid];
            g_env[bb * NF_ + k] = s * (1.f / (float)T_);
        }
    }
    if (k0 == 0) {   // mel gather: all centers are in [0, 25)
        int m = tid / T_;
        int tt = tid - m * T_;
        float* melb = mel + (size_t)bb * NMEL_ * T_;
        while (m < NMEL_) {
            int c = g_centers[m];
            melb[m * T_ + tt] = (c >= 0) ? tile[tt][c] : 0.f;
            m += 3; tt += 34;
            if (tt >= T_) { tt -= T_; ++m; }
        }
    }
}

// ---------------- BN stats: single pass, float partials (sum, sumsq) ----------------
__global__ void __launch_bounds__(256) k_bnstats(const float* __restrict__ w5, const float* __restrict__ b5,
                                                 const float* __restrict__ w7, const float* __restrict__ b7) {
    const int b = blockIdx.x, tid = threadIdx.x;
    __shared__ float e[NF_ + 4];
    __shared__ float cp[24];
    for (int i = tid; i < NF_ + 4; i += 256) {
        int f = i - 2;
        e[i] = (f >= 0 && f < NF_) ? g_env[b * NF_ + f] : 0.f;
    }
    if (tid < 24) {
        int j = tid - 3;
        cp[tid] = (j >= 0 && j < 18) ? g_env[b * NF_ + 6 + j] : 0.f;
    }
    __syncthreads();

    {
        const int o = tid >> 3, sub = tid & 7;
        float wv[5];
#pragma unroll
        for (int k = 0; k < 5; ++k) wv[k] = w5[o * 5 + k];
        const float bb = b5[o];
        float s = 0.f, s2 = 0.f;
        for (int l = sub; l < NF_; l += 8) {
            float y = bb;
#pragma unroll
            for (int k = 0; k < 5; ++k) y += wv[k] * e[l + k];
            s += y; s2 += y * y;
        }
#pragma unroll
        for (int d = 4; d; d >>= 1) {
            s  += __shfl_down_sync(0xffffffffu, s,  d, 8);
            s2 += __shfl_down_sync(0xffffffffu, s2, d, 8);
        }
        if (sub == 0) { g_psumS[b * 32 + o] = s; g_psumS2[b * 32 + o] = s2; }
    }
    if (tid < 24) {
        const int oc = tid;
        float s = 0.f, s2 = 0.f;
        for (int l = 0; l < 18; ++l) {
            float y = b7[oc];
#pragma unroll
            for (int k = 0; k < 7; ++k) y += w7[oc * 7 + k] * cp[l + k];
            s += y; s2 += y * y;
        }
        g_psumC[b * 24 + oc] = s; g_psumC2[b * 24 + oc] = s2;
    }
}

// ---------------- reduce: parallel fp64 mean/var -> BN scale/shift ----------------
__global__ void __launch_bounds__(896) k_reduce(const float* __restrict__ gS, const float* __restrict__ btS,
                                                const float* __restrict__ gC, const float* __restrict__ btC) {
    const int t = threadIdx.x;
    const int ch = t >> 4, sub = t & 15;
    if (ch >= 56) return;
    double s = 0.0, s2 = 0.0;
    if (ch < 32) {
        for (int j = 0; j < 32; ++j) {
            int b = sub + 16 * j;
            s  += (double)g_psumS[b * 32 + ch];
            s2 += (double)g_psumS2[b * 32 + ch];
        }
    } else {
        int o = ch - 32;
        for (int j = 0; j < 32; ++j) {
            int b = sub + 16 * j;
            s  += (double)g_psumC[b * 24 + o];
            s2 += (double)g_psumC2[b * 24 + o];
        }
    }
#pragma unroll
    for (int d = 8; d; d >>= 1) {
        s  += __shfl_down_sync(0xffffffffu, s,  d, 16);
        s2 += __shfl_down_sync(0xffffffffu, s2, d, 16);
    }
    if (sub == 0) {
        if (ch < 32) {
            double N = (double)B_ * (double)NF_;
            double m = s / N;
            double var = s2 / N - m * m;
            float a = gS[ch] * rsqrtf((float)var + 1e-5f);
            g_aS[ch] = a; g_cS[ch] = btS[ch] - (float)m * a;
        } else {
            int o = ch - 32;
            double N = (double)B_ * 18.0;
            double m = s / N;
            double var = s2 / N - m * m;
            float a = gC[o] * rsqrtf((float)var + 1e-5f);
            g_aC[o] = a; g_cC[o] = btC[o] - (float)m * a;
        }
    }
}

// ---------------- finalize: spectral out, cfeat, rfeat ----------------
__global__ void __launch_bounds__(256) k_final(const float* __restrict__ w5, const float* __restrict__ b5,
                                               const float* __restrict__ w7, const float* __restrict__ b7,
                                               const float* __restrict__ w1, const float* __restrict__ b1,
                                               const float* __restrict__ w2, const float* __restrict__ b2,
                                               float* __restrict__ outSpectral,
                                               float* __restrict__ outR,
                                               float* __restrict__ outC) {
    const int b = blockIdx.x, tid = threadIdx.x;
    __shared__ float e[NF_ + 4];
    __shared__ float cp[24];
    __shared__ float ws5[160], bs5[32], aSs[32], cSs[32];
    __shared__ float rpp[9];
    __shared__ float r1p[16][7];

    for (int i = tid; i < NF_ + 4; i += 256) {
        int f = i - 2;
        e[i] = (f >= 0 && f < NF_) ? g_env[b * NF_ + f] : 0.f;
    }
    if (tid < 24) {
        int j = tid - 3;
        cp[tid] = (j >= 0 && j < 18) ? g_env[b * NF_ + 6 + j] : 0.f;
    }
    if (tid < 160) ws5[tid] = w5[tid];
    if (tid < 32) { bs5[tid] = b5[tid]; aSs[tid] = g_aS[tid]; cSs[tid] = g_cS[tid]; }
    if (tid < 9) {
        int j = tid - 2;
        rpp[tid] = (j >= 0 && j < 4) ? g_env[b * NF_ + j] : 0.f;
    }
    if (tid < 16) { r1p[tid][0] = 0.f; r1p[tid][6] = 0.f; }
    __syncthreads();

    if (tid < 80) {
        int i = tid / 5, l = tid % 5;
        float y = b1[i];
#pragma unroll
        for (int k = 0; k < 5; ++k) y += w1[i * 5 + k] * rpp[l + k];
        r1p[i][l + 1] = fmaxf(0.f, y);
    }

    for (int idx = tid; idx < 32 * NF_; idx += 256) {
        int o = idx / NF_, l = idx - o * NF_;
        float y = bs5[o];
#pragma unroll
        for (int k = 0; k < 5; ++k) y += ws5[o * 5 + k] * e[l + k];
        outSpectral[(size_t)b * 32 * NF_ + idx] = fmaxf(0.f, y * aSs[o] + cSs[o]);
    }

    if (tid < 32) {
        float val = 0.f;
        if (tid < 24) {
            const int oc = tid;
            const float a = g_aC[oc], c = g_cC[oc];
            float acc = 0.f;
            for (int l = 0; l < 18; ++l) {
                float y = b7[oc];
#pragma unroll
                for (int k = 0; k < 7; ++k) y += w7[oc * 7 + k] * cp[l + k];
                acc += fmaxf(0.f, y * a + c);
            }
            val = acc / 18.f;
        }
        outC[b * 32 + tid] = val;
    }
    __syncthreads();

    if (tid < 32) {
        const int o = tid;
        float acc = 5.f * b2[o];
        for (int i = 0; i < 16; ++i) {
#pragma unroll
            for (int l = 0; l < 5; ++l)
#pragma unroll
                for (int k = 0; k < 3; ++k)
                    acc += w2[o * 48 + i * 3 + k] * r1p[i][l + k];
        }
        outR[b * 32 + o] = acc * 0.2f;
    }
}

// ---------------- launch ----------------
extern "C" void kernel_launch(void* const* d_in, const int* in_sizes, int n_in,
                              void* d_out, int out_size) {
    (void)in_sizes; (void)n_in; (void)out_size;
    const float* x   = (const float*)d_in[0];
    const float* w5  = (const float*)d_in[1];
    const float* b5  = (const float*)d_in[2];
    const float* g5  = (const float*)d_in[3];
    const float* bt5 = (const float*)d_in[4];
    const float* w7  = (const float*)d_in[5];
    const float* b7  = (const float*)d_in[6];
    const float* g7  = (const float*)d_in[7];
    const float* bt7 = (const float*)d_in[8];
    const float* w1  = (const float*)d_in[9];
    const float* b1  = (const float*)d_in[10];
    const float* w2  = (const float*)d_in[11];
    const float* b2  = (const float*)d_in[12];

    float* out         = (float*)d_out;
    float* outMel      = out;
    float* outSpectral = outMel + (size_t)B_ * 64 * T_;
    float* outR        = outSpectral + (size_t)B_ * 32 * NF_;
    float* outC        = outR + (size_t)B_ * 32;
    float* outSpec     = outC + (size_t)B_ * 32;

    k_init<<<8, 128>>>();
    k_spec<<<B_ * T_ / 2, 128>>>(x);
    k_transpose<<<B_ * 8, 256>>>(outSpec, outMel);
    k_bnstats<<<B_, 256>>>(w5, b5, w7, b7);
    k_reduce<<<1, 896>>>(g5, bt5, g7, bt7);
    k_final<<<B_, 256>>>(w5, b5, w7, b7, w1, b1, w2, b2, outSpectral, outR, outC);
}